// round 1
// baseline (speedup 1.0000x reference)
#include <cuda_runtime.h>

#define BATCH 16
#define SEQ   1024
#define EMBED 1280
#define NHEAD 16
#define HDIM  80
#define QKSCALE 0.111803398874989485f   // 80^-0.5

#define NTOK  (BATCH * SEQ)     // 16384
#define QKV_N (3 * EMBED)       // 3840

// ---------------- scratch (device globals; no runtime allocation) ----------
__device__ float g_q[(size_t)BATCH * NHEAD * SEQ * HDIM];   // [B,H,S,D], pre-scaled
__device__ float g_k[(size_t)BATCH * NHEAD * SEQ * HDIM];
__device__ float g_v[(size_t)BATCH * NHEAD * SEQ * HDIM];
__device__ float g_ctx[(size_t)NTOK * EMBED];               // [B,S,E]

// ============================================================================
// Kernel 1: QKV GEMM  C[16384,3840] = X[16384,1280] @ W[1280,3840] + b
// epilogue scatters into g_q/g_k/g_v in [B,H,S,D] layout, Q scaled.
// BM=BN=128, BK=8, 256 threads, 8x8 microtile (4+4 split).
// ============================================================================
__global__ __launch_bounds__(256) void qkv_gemm_kernel(
    const float* __restrict__ X, const float* __restrict__ W,
    const float* __restrict__ bias)
{
    __shared__ float sA[8][128];   // transposed A tile: sA[k][m]
    __shared__ float sB[8][128];

    const int tid = threadIdx.x;
    const int tx = tid & 15;
    const int ty = tid >> 4;
    const int m0 = blockIdx.y * 128;
    const int n0 = blockIdx.x * 128;

    float acc[8][8];
#pragma unroll
    for (int i = 0; i < 8; i++)
#pragma unroll
        for (int j = 0; j < 8; j++) acc[i][j] = 0.f;

    const int arow = tid >> 1;
    const int akc  = (tid & 1) * 4;
    const int brow = tid >> 5;
    const int bcol = (tid & 31) * 4;

    for (int k0 = 0; k0 < EMBED; k0 += 8) {
        float4 av = *(const float4*)(X + (size_t)(m0 + arow) * EMBED + k0 + akc);
        float4 bv = *(const float4*)(W + (size_t)(k0 + brow) * QKV_N + n0 + bcol);
        __syncthreads();   // protect previous iteration's reads
        sA[akc + 0][arow] = av.x;
        sA[akc + 1][arow] = av.y;
        sA[akc + 2][arow] = av.z;
        sA[akc + 3][arow] = av.w;
        *(float4*)&sB[brow][bcol] = bv;
        __syncthreads();
#pragma unroll
        for (int k = 0; k < 8; k++) {
            float4 a0 = *(const float4*)&sA[k][ty * 4];
            float4 a1 = *(const float4*)&sA[k][ty * 4 + 64];
            float4 b0 = *(const float4*)&sB[k][tx * 4];
            float4 b1 = *(const float4*)&sB[k][tx * 4 + 64];
            float a[8] = {a0.x, a0.y, a0.z, a0.w, a1.x, a1.y, a1.z, a1.w};
            float b[8] = {b0.x, b0.y, b0.z, b0.w, b1.x, b1.y, b1.z, b1.w};
#pragma unroll
            for (int i = 0; i < 8; i++)
#pragma unroll
                for (int j = 0; j < 8; j++) acc[i][j] = fmaf(a[i], b[j], acc[i][j]);
        }
    }

    // epilogue: bias add + scatter to [B,H,S,D]
#pragma unroll
    for (int i = 0; i < 8; i++) {
        int gm = m0 + ((i < 4) ? (ty * 4 + i) : (60 + ty * 4 + i));
        int bb = gm >> 10;
        int ss = gm & 1023;
#pragma unroll
        for (int j = 0; j < 8; j++) {
            int gn = n0 + ((j < 4) ? (tx * 4 + j) : (60 + tx * 4 + j));
            float v = acc[i][j] + bias[gn];
            int which = gn / EMBED;
            int rem   = gn - which * EMBED;
            int h = rem / HDIM;
            int d = rem - h * HDIM;
            size_t off = (((size_t)bb * NHEAD + h) * SEQ + ss) * HDIM + d;
            if (which == 0)      g_q[off] = v * QKSCALE;
            else if (which == 1) g_k[off] = v;
            else                 g_v[off] = v;
        }
    }
}

// ============================================================================
// Kernel 2: flash attention. One CTA per (b,h, 64-query tile).
// 256 threads: tq=tid/16 (query group of 4 rows), tk=tid%16.
// Scores: 64x64x80 register-tiled GEMM from transposed smem (float4 loads).
// Online softmax with width-16 shuffle reductions. PV register-tiled.
// ============================================================================
__global__ __launch_bounds__(256) void attn_kernel()
{
    extern __shared__ float sm[];
    float* sQT = sm;                 // [80][68]  Q transposed (d-major)
    float* sKT = sQT + 80 * 68;      // [80][68]  K transposed
    float* sV  = sKT + 80 * 68;      // [64][84]  V row-major
    float* sST = sV  + 64 * 84;      // [64][68]  P transposed (key-major)

    const int tid = threadIdx.x;
    const int tk = tid & 15;
    const int tq = tid >> 4;
    const int bh = blockIdx.y;
    const int q0 = blockIdx.x * 64;
    const size_t qbase = ((size_t)bh * SEQ + q0) * HDIM;

    // load Q tile transposed (Q is already pre-scaled)
    for (int idx = tid; idx < 64 * 80; idx += 256) {
        int q = idx / 80;
        int d = idx - q * 80;
        sQT[d * 68 + q] = g_q[qbase + idx];
    }

    float m[4], l[4], o[4][5];
#pragma unroll
    for (int i = 0; i < 4; i++) {
        m[i] = -1e30f;
        l[i] = 0.f;
#pragma unroll
        for (int j = 0; j < 5; j++) o[i][j] = 0.f;
    }

    for (int kt = 0; kt < 16; kt++) {
        __syncthreads();   // previous PV/scores reads done (also covers Q store)
        const size_t kvbase = ((size_t)bh * SEQ + kt * 64) * HDIM;
        for (int idx = tid; idx < 64 * 80; idx += 256) {
            int r = idx / 80;
            int d = idx - r * 80;
            sKT[d * 68 + r] = g_k[kvbase + idx];
            sV[r * 84 + d]  = g_v[kvbase + idx];
        }
        __syncthreads();

        // ---- scores: acc[i][j] = sum_d Q[q0+tq*4+i][d] * K[kt*64+tk*4+j][d]
        float acc[4][4];
#pragma unroll
        for (int i = 0; i < 4; i++)
#pragma unroll
            for (int j = 0; j < 4; j++) acc[i][j] = 0.f;

#pragma unroll 8
        for (int d = 0; d < 80; d++) {
            float4 a = *(const float4*)(sQT + d * 68 + tq * 4);
            float4 b = *(const float4*)(sKT + d * 68 + tk * 4);
            float av[4] = {a.x, a.y, a.z, a.w};
            float bv[4] = {b.x, b.y, b.z, b.w};
#pragma unroll
            for (int i = 0; i < 4; i++)
#pragma unroll
                for (int j = 0; j < 4; j++)
                    acc[i][j] = fmaf(av[i], bv[j], acc[i][j]);
        }

        // ---- online softmax (row stats reduced across the 16 tk lanes)
#pragma unroll
        for (int i = 0; i < 4; i++) {
            float mx = fmaxf(fmaxf(acc[i][0], acc[i][1]), fmaxf(acc[i][2], acc[i][3]));
#pragma unroll
            for (int off = 8; off > 0; off >>= 1)
                mx = fmaxf(mx, __shfl_xor_sync(0xffffffffu, mx, off));
            float mnew = fmaxf(m[i], mx);
            float p0 = __expf(acc[i][0] - mnew);
            float p1 = __expf(acc[i][1] - mnew);
            float p2 = __expf(acc[i][2] - mnew);
            float p3 = __expf(acc[i][3] - mnew);
            float sum = (p0 + p1) + (p2 + p3);
#pragma unroll
            for (int off = 8; off > 0; off >>= 1)
                sum += __shfl_xor_sync(0xffffffffu, sum, off);
            float alpha = __expf(m[i] - mnew);
            l[i] = l[i] * alpha + sum;
            m[i] = mnew;
#pragma unroll
            for (int j = 0; j < 5; j++) o[i][j] *= alpha;
            // store P transposed: sST[key][query]
            sST[(tk * 4 + 0) * 68 + tq * 4 + i] = p0;
            sST[(tk * 4 + 1) * 68 + tq * 4 + i] = p1;
            sST[(tk * 4 + 2) * 68 + tq * 4 + i] = p2;
            sST[(tk * 4 + 3) * 68 + tq * 4 + i] = p3;
        }
        __syncthreads();

        // ---- PV: o[i][*] += P[q][kk] * V[kk][*], cols tk*4..tk*4+3 and 64+tk
#pragma unroll 8
        for (int kk = 0; kk < 64; kk++) {
            float4 p  = *(const float4*)(sST + kk * 68 + tq * 4);
            float4 v0 = *(const float4*)(sV  + kk * 84 + tk * 4);
            float  v1 = sV[kk * 84 + 64 + tk];
            float pv[4] = {p.x, p.y, p.z, p.w};
#pragma unroll
            for (int i = 0; i < 4; i++) {
                o[i][0] = fmaf(pv[i], v0.x, o[i][0]);
                o[i][1] = fmaf(pv[i], v0.y, o[i][1]);
                o[i][2] = fmaf(pv[i], v0.z, o[i][2]);
                o[i][3] = fmaf(pv[i], v0.w, o[i][3]);
                o[i][4] = fmaf(pv[i], v1,   o[i][4]);
            }
        }
    }

    // ---- write context in [B,S,E] layout
    const int b = bh >> 4;
    const int h = bh & 15;
#pragma unroll
    for (int i = 0; i < 4; i++) {
        float inv = 1.0f / l[i];
        int q = q0 + tq * 4 + i;
        float* dst = g_ctx + ((size_t)(b * SEQ + q)) * EMBED + h * HDIM;
        dst[tk * 4 + 0] = o[i][0] * inv;
        dst[tk * 4 + 1] = o[i][1] * inv;
        dst[tk * 4 + 2] = o[i][2] * inv;
        dst[tk * 4 + 3] = o[i][3] * inv;
        dst[64 + tk]    = o[i][4] * inv;
    }
}

// ============================================================================
// Kernel 3: output projection  out[16384,1280] = ctx @ W_proj + b_proj
// ============================================================================
__global__ __launch_bounds__(256) void proj_gemm_kernel(
    const float* __restrict__ W, const float* __restrict__ bias,
    float* __restrict__ out)
{
    __shared__ float sA[8][128];
    __shared__ float sB[8][128];

    const int tid = threadIdx.x;
    const int tx = tid & 15;
    const int ty = tid >> 4;
    const int m0 = blockIdx.y * 128;
    const int n0 = blockIdx.x * 128;

    float acc[8][8];
#pragma unroll
    for (int i = 0; i < 8; i++)
#pragma unroll
        for (int j = 0; j < 8; j++) acc[i][j] = 0.f;

    const int arow = tid >> 1;
    const int akc  = (tid & 1) * 4;
    const int brow = tid >> 5;
    const int bcol = (tid & 31) * 4;

    for (int k0 = 0; k0 < EMBED; k0 += 8) {
        float4 av = *(const float4*)(g_ctx + (size_t)(m0 + arow) * EMBED + k0 + akc);
        float4 bv = *(const float4*)(W + (size_t)(k0 + brow) * EMBED + n0 + bcol);
        __syncthreads();
        sA[akc + 0][arow] = av.x;
        sA[akc + 1][arow] = av.y;
        sA[akc + 2][arow] = av.z;
        sA[akc + 3][arow] = av.w;
        *(float4*)&sB[brow][bcol] = bv;
        __syncthreads();
#pragma unroll
        for (int k = 0; k < 8; k++) {
            float4 a0 = *(const float4*)&sA[k][ty * 4];
            float4 a1 = *(const float4*)&sA[k][ty * 4 + 64];
            float4 b0 = *(const float4*)&sB[k][tx * 4];
            float4 b1 = *(const float4*)&sB[k][tx * 4 + 64];
            float a[8] = {a0.x, a0.y, a0.z, a0.w, a1.x, a1.y, a1.z, a1.w};
            float b[8] = {b0.x, b0.y, b0.z, b0.w, b1.x, b1.y, b1.z, b1.w};
#pragma unroll
            for (int i = 0; i < 8; i++)
#pragma unroll
                for (int j = 0; j < 8; j++) acc[i][j] = fmaf(a[i], b[j], acc[i][j]);
        }
    }

    float bj0[4], bj1[4];
#pragma unroll
    for (int c = 0; c < 4; c++) {
        bj0[c] = bias[n0 + tx * 4 + c];
        bj1[c] = bias[n0 + 64 + tx * 4 + c];
    }
#pragma unroll
    for (int i = 0; i < 8; i++) {
        int gm = m0 + ((i < 4) ? (ty * 4 + i) : (60 + ty * 4 + i));
        float* dst = out + (size_t)gm * EMBED + n0;
        float4 v0 = make_float4(acc[i][0] + bj0[0], acc[i][1] + bj0[1],
                                acc[i][2] + bj0[2], acc[i][3] + bj0[3]);
        float4 v1 = make_float4(acc[i][4] + bj1[0], acc[i][5] + bj1[1],
                                acc[i][6] + bj1[2], acc[i][7] + bj1[3]);
        *(float4*)(dst + tx * 4)      = v0;
        *(float4*)(dst + 64 + tx * 4) = v1;
    }
}

// ============================================================================
extern "C" void kernel_launch(void* const* d_in, const int* in_sizes, int n_in,
                              void* d_out, int out_size)
{
    const float* x      = (const float*)d_in[0];
    const float* w_qkv  = (const float*)d_in[1];
    const float* b_qkv  = (const float*)d_in[2];
    const float* w_proj = (const float*)d_in[3];
    const float* b_proj = (const float*)d_in[4];
    float* out = (float*)d_out;

    dim3 g1(QKV_N / 128, NTOK / 128);
    qkv_gemm_kernel<<<g1, 256>>>(x, w_qkv, b_qkv);

    const int attn_smem = (80 * 68 * 2 + 64 * 84 + 64 * 68) * (int)sizeof(float); // 82432 B
    cudaFuncSetAttribute(attn_kernel, cudaFuncAttributeMaxDynamicSharedMemorySize, attn_smem);
    dim3 g2(SEQ / 64, BATCH * NHEAD);
    attn_kernel<<<g2, 256, attn_smem>>>();

    dim3 g3(EMBED / 128, NTOK / 128);
    proj_gemm_kernel<<<g3, 256>>>(w_proj, b_proj, out);
}

// round 4
// speedup vs baseline: 1.6853x; 1.6853x over previous
#include <cuda_runtime.h>
#include <cuda_bf16.h>
#include <cstdint>

#define BATCH 16
#define SEQ   1024
#define EMBED 1280
#define NHEAD 16
#define HDIM  80
#define QKSCALE 0.111803398874989485f   // 80^-0.5

#define NTOK  (BATCH * SEQ)     // 16384
#define QKV_N (3 * EMBED)       // 3840

#define BM 128
#define BN 128
#define BK 64                   // bf16 per K-iter (128 B/row)
#define KTOT EMBED
#define NITER (KTOT / BK)       // 20

// ---------------- scratch (device globals; no runtime allocation) ----------
__device__ __align__(256) float g_q[(size_t)BATCH * NHEAD * SEQ * HDIM];
__device__ __align__(256) float g_k[(size_t)BATCH * NHEAD * SEQ * HDIM];
__device__ __align__(256) float g_v[(size_t)BATCH * NHEAD * SEQ * HDIM];
__device__ __align__(256) __nv_bfloat16 g_xh[(size_t)NTOK * EMBED];
__device__ __align__(256) __nv_bfloat16 g_xl[(size_t)NTOK * EMBED];
__device__ __align__(256) __nv_bfloat16 g_wqh[(size_t)QKV_N * EMBED];  // [N][K]
__device__ __align__(256) __nv_bfloat16 g_wql[(size_t)QKV_N * EMBED];
__device__ __align__(256) __nv_bfloat16 g_wph[(size_t)EMBED * EMBED];  // [N][K]
__device__ __align__(256) __nv_bfloat16 g_wpl[(size_t)EMBED * EMBED];
__device__ __align__(256) __nv_bfloat16 g_ch[(size_t)NTOK * EMBED];
__device__ __align__(256) __nv_bfloat16 g_cl[(size_t)NTOK * EMBED];

// ---------------- helpers ----------------------------------------------
__device__ __forceinline__ uint32_t smem_u32(const void* p) {
    uint32_t a;
    asm("{ .reg .u64 t; cvta.to.shared.u64 t, %1; cvt.u32.u64 %0, t; }" : "=r"(a) : "l"(p));
    return a;
}

__device__ __forceinline__ uint32_t swz(uint32_t off) {  // SW128 swizzle
    return off ^ (((off >> 7) & 7) << 4);
}

#define CP_ASYNC16(dst, src) \
    asm volatile("cp.async.cg.shared.global [%0], [%1], 16;" :: "r"(dst), "l"(src))
#define CP_COMMIT() asm volatile("cp.async.commit_group;")
#define CP_WAIT(N)  asm volatile("cp.async.wait_group %0;" :: "n"(N))

__device__ __forceinline__ void ldsm_x4(uint32_t addr, uint32_t& r0, uint32_t& r1,
                                        uint32_t& r2, uint32_t& r3) {
    asm volatile("ldmatrix.sync.aligned.m8n8.x4.shared.b16 {%0,%1,%2,%3}, [%4];"
                 : "=r"(r0), "=r"(r1), "=r"(r2), "=r"(r3) : "r"(addr));
}

__device__ __forceinline__ void mma16816(float* c, const uint32_t* a, const uint32_t* b) {
    asm volatile(
        "mma.sync.aligned.m16n8k16.row.col.f32.bf16.bf16.f32 "
        "{%0,%1,%2,%3}, {%4,%5,%6,%7}, {%8,%9}, {%0,%1,%2,%3};"
        : "+f"(c[0]), "+f"(c[1]), "+f"(c[2]), "+f"(c[3])
        : "r"(a[0]), "r"(a[1]), "r"(a[2]), "r"(a[3]), "r"(b[0]), "r"(b[1]));
}

// ============================================================================
// Prep 1: split X (fp32 -> bf16 hi + lo)
// ============================================================================
__global__ __launch_bounds__(256) void xsplit_kernel(const float* __restrict__ X,
                                                     __nv_bfloat16* __restrict__ H,
                                                     __nv_bfloat16* __restrict__ L,
                                                     int n4)
{
    int i = blockIdx.x * 256 + threadIdx.x;
    if (i >= n4) return;
    float4 v = ((const float4*)X)[i];
    __nv_bfloat16 h0 = __float2bfloat16_rn(v.x), h1 = __float2bfloat16_rn(v.y);
    __nv_bfloat16 h2 = __float2bfloat16_rn(v.z), h3 = __float2bfloat16_rn(v.w);
    __nv_bfloat16 l0 = __float2bfloat16_rn(v.x - __bfloat162float(h0));
    __nv_bfloat16 l1 = __float2bfloat16_rn(v.y - __bfloat162float(h1));
    __nv_bfloat16 l2 = __float2bfloat16_rn(v.z - __bfloat162float(h2));
    __nv_bfloat16 l3 = __float2bfloat16_rn(v.w - __bfloat162float(h3));
    __nv_bfloat162* Hp = (__nv_bfloat162*)H;
    __nv_bfloat162* Lp = (__nv_bfloat162*)L;
    Hp[i * 2 + 0] = __nv_bfloat162(h0, h1);
    Hp[i * 2 + 1] = __nv_bfloat162(h2, h3);
    Lp[i * 2 + 0] = __nv_bfloat162(l0, l1);
    Lp[i * 2 + 1] = __nv_bfloat162(l2, l3);
}

// ============================================================================
// Prep 2: transpose + split W ([K][N] fp32 -> [N][K] bf16 hi/lo)
// ============================================================================
__global__ __launch_bounds__(256) void wsplit_kernel(const float* __restrict__ W,
                                                     __nv_bfloat16* __restrict__ TH,
                                                     __nv_bfloat16* __restrict__ TL,
                                                     int K, int N)
{
    __shared__ float t[32][33];
    int tx = threadIdx.x & 31, ty = threadIdx.x >> 5;
    int n0 = blockIdx.x * 32, k0 = blockIdx.y * 32;
#pragma unroll
    for (int i = 0; i < 4; i++)
        t[ty + i * 8][tx] = W[(size_t)(k0 + ty + i * 8) * N + n0 + tx];
    __syncthreads();
#pragma unroll
    for (int i = 0; i < 4; i++) {
        int n = ty + i * 8;
        float v = t[tx][n];
        __nv_bfloat16 h = __float2bfloat16_rn(v);
        __nv_bfloat16 l = __float2bfloat16_rn(v - __bfloat162float(h));
        TH[(size_t)(n0 + n) * K + k0 + tx] = h;
        TL[(size_t)(n0 + n) * K + k0 + tx] = l;
    }
}

// ============================================================================
// 3-term bf16 GEMM via mma.sync:  C[M,N] = A[M,1280] @ B^T  (B stored [N][1280])
// EPI=0: QKV epilogue (bias, scale Q, scatter to g_q/g_k/g_v)
// EPI=1: proj epilogue (bias, write to out)
// ============================================================================
template<int EPI>
__global__ __launch_bounds__(256, 1) void mm3_kernel(
    const __nv_bfloat16* __restrict__ Ah, const __nv_bfloat16* __restrict__ Al,
    const __nv_bfloat16* __restrict__ Bh, const __nv_bfloat16* __restrict__ Bl,
    const float* __restrict__ bias, float* __restrict__ out)
{
    extern __shared__ char smem[];
    const uint32_t sb = smem_u32(smem);
    const int tid = threadIdx.x;
    const int lane = tid & 31;
    const int wid = tid >> 5;
    const int wm = wid & 1;          // 2 warps along M
    const int wn = wid >> 1;         // 4 warps along N
    const int m0 = blockIdx.y * BM;
    const int n0 = blockIdx.x * BN;

    const int TSZ = BM * 128;        // 16384 B per half-tile (128 rows x 128 B)
    const int STG = 4 * TSZ;         // Ah, Al, Bh, Bl
    // stage s at sb + s*STG

    float acc[4][4][4];
#pragma unroll
    for (int i = 0; i < 4; i++)
#pragma unroll
        for (int j = 0; j < 4; j++)
#pragma unroll
            for (int e = 0; e < 4; e++) acc[i][j][e] = 0.f;

    // --- async tile loader: 16 cp.async x 16B per thread per stage
    auto load_stage = [&](int buf, int k0) {
        const uint32_t bb = sb + buf * STG;
#pragma unroll
        for (int i = 0; i < 4; i++) {
            int idx = tid + i * 256;          // 1024 chunks over [128 rows][8 units]
            int r = idx >> 3, c = idx & 7;
            uint32_t so = swz(r * 128 + c * 16);
            const char* pah = (const char*)(Ah + (size_t)(m0 + r) * KTOT + k0 + c * 8);
            const char* pal = (const char*)(Al + (size_t)(m0 + r) * KTOT + k0 + c * 8);
            const char* pbh = (const char*)(Bh + (size_t)(n0 + r) * KTOT + k0 + c * 8);
            const char* pbl = (const char*)(Bl + (size_t)(n0 + r) * KTOT + k0 + c * 8);
            CP_ASYNC16(bb + 0 * TSZ + so, pah);
            CP_ASYNC16(bb + 1 * TSZ + so, pal);
            CP_ASYNC16(bb + 2 * TSZ + so, pbh);
            CP_ASYNC16(bb + 3 * TSZ + so, pbl);
        }
        CP_COMMIT();
    };

    // ldmatrix lane addressing
    const int a_m = ((lane >> 3) & 1) * 8 + (lane & 7);
    const int a_k = ((lane >> 4) & 1) * 16;
    const int b_n = ((lane >> 4) & 1) * 8 + (lane & 7);
    const int b_k = ((lane >> 3) & 1) * 16;

    load_stage(0, 0);

    for (int it = 0; it < NITER; it++) {
        const int buf = it & 1;
        if (it + 1 < NITER) { load_stage(buf ^ 1, (it + 1) * BK); CP_WAIT(1); }
        else                { CP_WAIT(0); }
        __syncthreads();

        const uint32_t bb = sb + buf * STG;
        const uint32_t sAh = bb, sAl = bb + TSZ, sBh = bb + 2 * TSZ, sBl = bb + 3 * TSZ;

#pragma unroll
        for (int ks = 0; ks < 4; ks++) {
            uint32_t ah[4][4], al[4][4], bh[2][4], bl[2][4];
#pragma unroll
            for (int mi = 0; mi < 4; mi++) {
                uint32_t off = swz((wm * 64 + mi * 16 + a_m) * 128 + ks * 32 + a_k);
                ldsm_x4(sAh + off, ah[mi][0], ah[mi][1], ah[mi][2], ah[mi][3]);
                ldsm_x4(sAl + off, al[mi][0], al[mi][1], al[mi][2], al[mi][3]);
            }
#pragma unroll
            for (int np = 0; np < 2; np++) {
                uint32_t off = swz((wn * 32 + np * 16 + b_n) * 128 + ks * 32 + b_k);
                ldsm_x4(sBh + off, bh[np][0], bh[np][1], bh[np][2], bh[np][3]);
                ldsm_x4(sBl + off, bl[np][0], bl[np][1], bl[np][2], bl[np][3]);
            }
#pragma unroll
            for (int mi = 0; mi < 4; mi++)
#pragma unroll
                for (int np = 0; np < 2; np++)
#pragma unroll
                    for (int ns = 0; ns < 2; ns++) {
                        float* c = acc[mi][np * 2 + ns];
                        mma16816(c, ah[mi], &bh[np][ns * 2]);   // hi*hi
                        mma16816(c, ah[mi], &bl[np][ns * 2]);   // hi*lo
                        mma16816(c, al[mi], &bh[np][ns * 2]);   // lo*hi
                    }
        }
        __syncthreads();
    }

    // ---- epilogue
    const int mrow = lane >> 2;          // 0..7
    const int ncol = (lane & 3) * 2;     // 0,2,4,6
#pragma unroll
    for (int mi = 0; mi < 4; mi++) {
#pragma unroll
        for (int ni = 0; ni < 4; ni++) {
            int gn = n0 + wn * 32 + ni * 8 + ncol;
            float b0 = bias[gn], b1 = bias[gn + 1];
#pragma unroll
            for (int half = 0; half < 2; half++) {
                int gm = m0 + wm * 64 + mi * 16 + mrow + half * 8;
                float v0 = acc[mi][ni][half * 2 + 0] + b0;
                float v1 = acc[mi][ni][half * 2 + 1] + b1;
                if (EPI == 0) {
                    int which = gn / EMBED;   // uniform within CTA (BN=128 | 1280)
                    int rem = gn - which * EMBED;
                    int h = rem / HDIM, d = rem - h * HDIM;
                    int bb2 = gm >> 10, ss = gm & 1023;
                    float scale = (which == 0) ? QKSCALE : 1.0f;
                    float* dstbase = (which == 0) ? g_q : (which == 1) ? g_k : g_v;
                    float2 v = make_float2(v0 * scale, v1 * scale);
                    *(float2*)(dstbase + (((size_t)bb2 * NHEAD + h) * SEQ + ss) * HDIM + d) = v;
                } else {
                    *(float2*)(out + (size_t)gm * EMBED + gn) = make_float2(v0, v1);
                }
            }
        }
    }
}

// ============================================================================
// Flash attention (fp32 SIMT; ctx written as bf16 hi/lo for the proj GEMM)
// ============================================================================
__global__ __launch_bounds__(256) void attn_kernel()
{
    extern __shared__ float sm[];
    float* sQT = sm;
    float* sKT = sQT + 80 * 68;
    float* sV  = sKT + 80 * 68;
    float* sST = sV  + 64 * 84;

    const int tid = threadIdx.x;
    const int tk = tid & 15;
    const int tq = tid >> 4;
    const int bh = blockIdx.y;
    const int q0 = blockIdx.x * 64;
    const size_t qbase = ((size_t)bh * SEQ + q0) * HDIM;

    for (int idx = tid; idx < 64 * 80; idx += 256) {
        int q = idx / 80;
        int d = idx - q * 80;
        sQT[d * 68 + q] = g_q[qbase + idx];
    }

    float m[4], l[4], o[4][5];
#pragma unroll
    for (int i = 0; i < 4; i++) {
        m[i] = -1e30f; l[i] = 0.f;
#pragma unroll
        for (int j = 0; j < 5; j++) o[i][j] = 0.f;
    }

    for (int kt = 0; kt < 16; kt++) {
        __syncthreads();
        const size_t kvbase = ((size_t)bh * SEQ + kt * 64) * HDIM;
        for (int idx = tid; idx < 64 * 80; idx += 256) {
            int r = idx / 80;
            int d = idx - r * 80;
            sKT[d * 68 + r] = g_k[kvbase + idx];
            sV[r * 84 + d]  = g_v[kvbase + idx];
        }
        __syncthreads();

        float acc[4][4];
#pragma unroll
        for (int i = 0; i < 4; i++)
#pragma unroll
            for (int j = 0; j < 4; j++) acc[i][j] = 0.f;

#pragma unroll 8
        for (int d = 0; d < 80; d++) {
            float4 a = *(const float4*)(sQT + d * 68 + tq * 4);
            float4 b = *(const float4*)(sKT + d * 68 + tk * 4);
            float av[4] = {a.x, a.y, a.z, a.w};
            float bv[4] = {b.x, b.y, b.z, b.w};
#pragma unroll
            for (int i = 0; i < 4; i++)
#pragma unroll
                for (int j = 0; j < 4; j++)
                    acc[i][j] = fmaf(av[i], bv[j], acc[i][j]);
        }

#pragma unroll
        for (int i = 0; i < 4; i++) {
            float mx = fmaxf(fmaxf(acc[i][0], acc[i][1]), fmaxf(acc[i][2], acc[i][3]));
#pragma unroll
            for (int off = 8; off > 0; off >>= 1)
                mx = fmaxf(mx, __shfl_xor_sync(0xffffffffu, mx, off));
            float mnew = fmaxf(m[i], mx);
            float p0 = __expf(acc[i][0] - mnew);
            float p1 = __expf(acc[i][1] - mnew);
            float p2 = __expf(acc[i][2] - mnew);
            float p3 = __expf(acc[i][3] - mnew);
            float sum = (p0 + p1) + (p2 + p3);
#pragma unroll
            for (int off = 8; off > 0; off >>= 1)
                sum += __shfl_xor_sync(0xffffffffu, sum, off);
            float alpha = __expf(m[i] - mnew);
            l[i] = l[i] * alpha + sum;
            m[i] = mnew;
#pragma unroll
            for (int j = 0; j < 5; j++) o[i][j] *= alpha;
            sST[(tk * 4 + 0) * 68 + tq * 4 + i] = p0;
            sST[(tk * 4 + 1) * 68 + tq * 4 + i] = p1;
            sST[(tk * 4 + 2) * 68 + tq * 4 + i] = p2;
            sST[(tk * 4 + 3) * 68 + tq * 4 + i] = p3;
        }
        __syncthreads();

#pragma unroll 8
        for (int kk = 0; kk < 64; kk++) {
            float4 p  = *(const float4*)(sST + kk * 68 + tq * 4);
            float4 v0 = *(const float4*)(sV  + kk * 84 + tk * 4);
            float  v1 = sV[kk * 84 + 64 + tk];
            float pv[4] = {p.x, p.y, p.z, p.w};
#pragma unroll
            for (int i = 0; i < 4; i++) {
                o[i][0] = fmaf(pv[i], v0.x, o[i][0]);
                o[i][1] = fmaf(pv[i], v0.y, o[i][1]);
                o[i][2] = fmaf(pv[i], v0.z, o[i][2]);
                o[i][3] = fmaf(pv[i], v0.w, o[i][3]);
                o[i][4] = fmaf(pv[i], v1,   o[i][4]);
            }
        }
    }

    const int b = bh >> 4;
    const int h = bh & 15;
#pragma unroll
    for (int i = 0; i < 4; i++) {
        float inv = 1.0f / l[i];
        int q = q0 + tq * 4 + i;
        size_t base = ((size_t)(b * SEQ + q)) * EMBED + h * HDIM;
        float vals[5] = {o[i][0] * inv, o[i][1] * inv, o[i][2] * inv,
                         o[i][3] * inv, o[i][4] * inv};
        int offs[5] = {tk * 4 + 0, tk * 4 + 1, tk * 4 + 2, tk * 4 + 3, 64 + tk};
#pragma unroll
        for (int j = 0; j < 5; j++) {
            __nv_bfloat16 hi = __float2bfloat16_rn(vals[j]);
            __nv_bfloat16 lo = __float2bfloat16_rn(vals[j] - __bfloat162float(hi));
            g_ch[base + offs[j]] = hi;
            g_cl[base + offs[j]] = lo;
        }
    }
}

// ============================================================================
extern "C" void kernel_launch(void* const* d_in, const int* in_sizes, int n_in,
                              void* d_out, int out_size)
{
    const float* x      = (const float*)d_in[0];
    const float* w_qkv  = (const float*)d_in[1];
    const float* b_qkv  = (const float*)d_in[2];
    const float* w_proj = (const float*)d_in[3];
    const float* b_proj = (const float*)d_in[4];
    float* out = (float*)d_out;

    __nv_bfloat16 *xh, *xl, *wqh, *wql, *wph, *wpl, *ch, *cl;
    cudaGetSymbolAddress((void**)&xh,  g_xh);
    cudaGetSymbolAddress((void**)&xl,  g_xl);
    cudaGetSymbolAddress((void**)&wqh, g_wqh);
    cudaGetSymbolAddress((void**)&wql, g_wql);
    cudaGetSymbolAddress((void**)&wph, g_wph);
    cudaGetSymbolAddress((void**)&wpl, g_wpl);
    cudaGetSymbolAddress((void**)&ch,  g_ch);
    cudaGetSymbolAddress((void**)&cl,  g_cl);

    const int mm_smem = 2 * 4 * BM * 128;   // 131072 B
    cudaFuncSetAttribute(mm3_kernel<0>, cudaFuncAttributeMaxDynamicSharedMemorySize, mm_smem);
    cudaFuncSetAttribute(mm3_kernel<1>, cudaFuncAttributeMaxDynamicSharedMemorySize, mm_smem);
    const int attn_smem = (80 * 68 * 2 + 64 * 84 + 64 * 68) * (int)sizeof(float);
    cudaFuncSetAttribute(attn_kernel, cudaFuncAttributeMaxDynamicSharedMemorySize, attn_smem);

    // prep
    xsplit_kernel<<<(NTOK * EMBED / 4 + 255) / 256, 256>>>(x, xh, xl, NTOK * EMBED / 4);
    {
        dim3 g(QKV_N / 32, EMBED / 32);
        wsplit_kernel<<<g, 256>>>(w_qkv, wqh, wql, EMBED, QKV_N);
    }
    {
        dim3 g(EMBED / 32, EMBED / 32);
        wsplit_kernel<<<g, 256>>>(w_proj, wph, wpl, EMBED, EMBED);
    }

    // QKV GEMM
    {
        dim3 g(QKV_N / BN, NTOK / BM);
        mm3_kernel<0><<<g, 256, mm_smem>>>(xh, xl, wqh, wql, b_qkv, nullptr);
    }
    // attention
    {
        dim3 g(SEQ / 64, BATCH * NHEAD);
        attn_kernel<<<g, 256, attn_smem>>>();
    }
    // output projection
    {
        dim3 g(EMBED / BN, NTOK / BM);
        mm3_kernel<1><<<g, 256, mm_smem>>>(ch, cl, wph, wpl, b_proj, out);
    }
}

// round 6
// speedup vs baseline: 3.7974x; 2.2533x over previous
#include <cuda_runtime.h>
#include <cuda_bf16.h>
#include <cuda_fp16.h>
#include <cstdint>

#define BATCH 16
#define SEQ   1024
#define EMBED 1280
#define NHEAD 16
#define HDIM  80
#define QKSCALE 0.111803398874989485f   // 80^-0.5
#define QSC2 (0.111803398874989485f * 1.4426950408889634f)  // QKSCALE * log2(e)

#define NTOK  (BATCH * SEQ)     // 16384
#define QKV_N (3 * EMBED)       // 3840

#define BM 128
#define BN 128
#define BK 64
#define KTOT EMBED
#define NITER (KTOT / BK)       // 20

// ---------------- scratch -----------------------------------------------
__device__ __align__(256) __half g_qt[(size_t)BATCH * NHEAD * HDIM * SEQ];  // [B,H,D,S], pre-scaled by QSC2
__device__ __align__(256) __half g_kt[(size_t)BATCH * NHEAD * HDIM * SEQ];
__device__ __align__(256) __half g_vt[(size_t)BATCH * NHEAD * HDIM * SEQ];
__device__ __align__(256) __nv_bfloat16 g_xh[(size_t)NTOK * EMBED];
__device__ __align__(256) __nv_bfloat16 g_xl[(size_t)NTOK * EMBED];
__device__ __align__(256) __nv_bfloat16 g_wqh[(size_t)QKV_N * EMBED];
__device__ __align__(256) __nv_bfloat16 g_wql[(size_t)QKV_N * EMBED];
__device__ __align__(256) __nv_bfloat16 g_wph[(size_t)EMBED * EMBED];
__device__ __align__(256) __nv_bfloat16 g_wpl[(size_t)EMBED * EMBED];
__device__ __align__(256) __nv_bfloat16 g_ch[(size_t)NTOK * EMBED];
__device__ __align__(256) __nv_bfloat16 g_cl[(size_t)NTOK * EMBED];

// ---------------- helpers ----------------------------------------------
__device__ __forceinline__ uint32_t smem_u32(const void* p) {
    uint32_t a;
    asm("{ .reg .u64 t; cvta.to.shared.u64 t, %1; cvt.u32.u64 %0, t; }" : "=r"(a) : "l"(p));
    return a;
}
__device__ __forceinline__ uint32_t swz(uint32_t off) { return off ^ (((off >> 7) & 7) << 4); }

#define CP_ASYNC16(dst, src) \
    asm volatile("cp.async.cg.shared.global [%0], [%1], 16;" :: "r"(dst), "l"(src))
#define CP_COMMIT() asm volatile("cp.async.commit_group;")
#define CP_WAIT(N)  asm volatile("cp.async.wait_group %0;" :: "n"(N))

__device__ __forceinline__ void ldsm_x4(uint32_t addr, uint32_t& r0, uint32_t& r1,
                                        uint32_t& r2, uint32_t& r3) {
    asm volatile("ldmatrix.sync.aligned.m8n8.x4.shared.b16 {%0,%1,%2,%3}, [%4];"
                 : "=r"(r0), "=r"(r1), "=r"(r2), "=r"(r3) : "r"(addr));
}
__device__ __forceinline__ void ldsm_x4t(uint32_t addr, uint32_t& r0, uint32_t& r1,
                                         uint32_t& r2, uint32_t& r3) {
    asm volatile("ldmatrix.sync.aligned.m8n8.x4.trans.shared.b16 {%0,%1,%2,%3}, [%4];"
                 : "=r"(r0), "=r"(r1), "=r"(r2), "=r"(r3) : "r"(addr));
}
__device__ __forceinline__ void mma16816(float* c, const uint32_t* a, const uint32_t* b) {
    asm volatile(
        "mma.sync.aligned.m16n8k16.row.col.f32.bf16.bf16.f32 "
        "{%0,%1,%2,%3}, {%4,%5,%6,%7}, {%8,%9}, {%0,%1,%2,%3};"
        : "+f"(c[0]), "+f"(c[1]), "+f"(c[2]), "+f"(c[3])
        : "r"(a[0]), "r"(a[1]), "r"(a[2]), "r"(a[3]), "r"(b[0]), "r"(b[1]));
}
__device__ __forceinline__ void mma16816h(float* c, const uint32_t* a, const uint32_t* b) {
    asm volatile(
        "mma.sync.aligned.m16n8k16.row.col.f32.f16.f16.f32 "
        "{%0,%1,%2,%3}, {%4,%5,%6,%7}, {%8,%9}, {%0,%1,%2,%3};"
        : "+f"(c[0]), "+f"(c[1]), "+f"(c[2]), "+f"(c[3])
        : "r"(a[0]), "r"(a[1]), "r"(a[2]), "r"(a[3]), "r"(b[0]), "r"(b[1]));
}
__device__ __forceinline__ float ex2(float x) {
    float y; asm("ex2.approx.ftz.f32 %0, %1;" : "=f"(y) : "f"(x)); return y;
}
__device__ __forceinline__ uint32_t packh2(float x, float y) {
    uint32_t r;
    asm("{ .reg .f16 lo, hi; cvt.rn.f16.f32 lo, %1; cvt.rn.f16.f32 hi, %2; "
        "mov.b32 %0, {lo, hi}; }" : "=r"(r) : "f"(x), "f"(y));
    return r;
}

// ============================================================================
// Prep 1: split X (fp32 -> bf16 hi + lo)
// ============================================================================
__global__ __launch_bounds__(256) void xsplit_kernel(const float* __restrict__ X,
                                                     __nv_bfloat16* __restrict__ H,
                                                     __nv_bfloat16* __restrict__ L,
                                                     int n4)
{
    int i = blockIdx.x * 256 + threadIdx.x;
    if (i >= n4) return;
    float4 v = ((const float4*)X)[i];
    __nv_bfloat16 h0 = __float2bfloat16_rn(v.x), h1 = __float2bfloat16_rn(v.y);
    __nv_bfloat16 h2 = __float2bfloat16_rn(v.z), h3 = __float2bfloat16_rn(v.w);
    __nv_bfloat16 l0 = __float2bfloat16_rn(v.x - __bfloat162float(h0));
    __nv_bfloat16 l1 = __float2bfloat16_rn(v.y - __bfloat162float(h1));
    __nv_bfloat16 l2 = __float2bfloat16_rn(v.z - __bfloat162float(h2));
    __nv_bfloat16 l3 = __float2bfloat16_rn(v.w - __bfloat162float(h3));
    __nv_bfloat162* Hp = (__nv_bfloat162*)H;
    __nv_bfloat162* Lp = (__nv_bfloat162*)L;
    Hp[i * 2 + 0] = __nv_bfloat162(h0, h1);
    Hp[i * 2 + 1] = __nv_bfloat162(h2, h3);
    Lp[i * 2 + 0] = __nv_bfloat162(l0, l1);
    Lp[i * 2 + 1] = __nv_bfloat162(l2, l3);
}

// ============================================================================
// Prep 2: transpose + split W ([K][N] fp32 -> [N][K] bf16 hi/lo)
// ============================================================================
__global__ __launch_bounds__(256) void wsplit_kernel(const float* __restrict__ W,
                                                     __nv_bfloat16* __restrict__ TH,
                                                     __nv_bfloat16* __restrict__ TL,
                                                     int K, int N)
{
    __shared__ float t[32][33];
    int tx = threadIdx.x & 31, ty = threadIdx.x >> 5;
    int n0 = blockIdx.x * 32, k0 = blockIdx.y * 32;
#pragma unroll
    for (int i = 0; i < 4; i++)
        t[ty + i * 8][tx] = W[(size_t)(k0 + ty + i * 8) * N + n0 + tx];
    __syncthreads();
#pragma unroll
    for (int i = 0; i < 4; i++) {
        int n = ty + i * 8;
        float v = t[tx][n];
        __nv_bfloat16 h = __float2bfloat16_rn(v);
        __nv_bfloat16 l = __float2bfloat16_rn(v - __bfloat162float(h));
        TH[(size_t)(n0 + n) * K + k0 + tx] = h;
        TL[(size_t)(n0 + n) * K + k0 + tx] = l;
    }
}

// ============================================================================
// 3-term bf16 GEMM via mma.sync
// EPI=0: QKV epilogue -> writes Q^T/K^T/V^T fp16 [B,H,D,S] (Q pre-scaled by QSC2)
// EPI=1: proj epilogue (bias, fp32 out)
// ============================================================================
template<int EPI>
__global__ __launch_bounds__(256, 1) void mm3_kernel(
    const __nv_bfloat16* __restrict__ Ah, const __nv_bfloat16* __restrict__ Al,
    const __nv_bfloat16* __restrict__ Bh, const __nv_bfloat16* __restrict__ Bl,
    const float* __restrict__ bias, float* __restrict__ out)
{
    extern __shared__ char smem[];
    const uint32_t sb = smem_u32(smem);
    const int tid = threadIdx.x;
    const int lane = tid & 31;
    const int wid = tid >> 5;
    const int wm = wid & 1;
    const int wn = wid >> 1;
    const int m0 = blockIdx.y * BM;
    const int n0 = blockIdx.x * BN;

    const int TSZ = BM * 128;
    const int STG = 4 * TSZ;

    float acc[4][4][4];
#pragma unroll
    for (int i = 0; i < 4; i++)
#pragma unroll
        for (int j = 0; j < 4; j++)
#pragma unroll
            for (int e = 0; e < 4; e++) acc[i][j][e] = 0.f;

    auto load_stage = [&](int buf, int k0) {
        const uint32_t bb = sb + buf * STG;
#pragma unroll
        for (int i = 0; i < 4; i++) {
            int idx = tid + i * 256;
            int r = idx >> 3, c = idx & 7;
            uint32_t so = swz(r * 128 + c * 16);
            const char* pah = (const char*)(Ah + (size_t)(m0 + r) * KTOT + k0 + c * 8);
            const char* pal = (const char*)(Al + (size_t)(m0 + r) * KTOT + k0 + c * 8);
            const char* pbh = (const char*)(Bh + (size_t)(n0 + r) * KTOT + k0 + c * 8);
            const char* pbl = (const char*)(Bl + (size_t)(n0 + r) * KTOT + k0 + c * 8);
            CP_ASYNC16(bb + 0 * TSZ + so, pah);
            CP_ASYNC16(bb + 1 * TSZ + so, pal);
            CP_ASYNC16(bb + 2 * TSZ + so, pbh);
            CP_ASYNC16(bb + 3 * TSZ + so, pbl);
        }
        CP_COMMIT();
    };

    const int a_m = ((lane >> 3) & 1) * 8 + (lane & 7);
    const int a_k = ((lane >> 4) & 1) * 16;
    const int b_n = ((lane >> 4) & 1) * 8 + (lane & 7);
    const int b_k = ((lane >> 3) & 1) * 16;

    load_stage(0, 0);

    for (int it = 0; it < NITER; it++) {
        const int buf = it & 1;
        if (it + 1 < NITER) { load_stage(buf ^ 1, (it + 1) * BK); CP_WAIT(1); }
        else                { CP_WAIT(0); }
        __syncthreads();

        const uint32_t bb = sb + buf * STG;
        const uint32_t sAh = bb, sAl = bb + TSZ, sBh = bb + 2 * TSZ, sBl = bb + 3 * TSZ;

#pragma unroll
        for (int ks = 0; ks < 4; ks++) {
            uint32_t ah[4][4], al[4][4], bh[2][4], bl[2][4];
#pragma unroll
            for (int mi = 0; mi < 4; mi++) {
                uint32_t off = swz((wm * 64 + mi * 16 + a_m) * 128 + ks * 32 + a_k);
                ldsm_x4(sAh + off, ah[mi][0], ah[mi][1], ah[mi][2], ah[mi][3]);
                ldsm_x4(sAl + off, al[mi][0], al[mi][1], al[mi][2], al[mi][3]);
            }
#pragma unroll
            for (int np = 0; np < 2; np++) {
                uint32_t off = swz((wn * 32 + np * 16 + b_n) * 128 + ks * 32 + b_k);
                ldsm_x4(sBh + off, bh[np][0], bh[np][1], bh[np][2], bh[np][3]);
                ldsm_x4(sBl + off, bl[np][0], bl[np][1], bl[np][2], bl[np][3]);
            }
#pragma unroll
            for (int mi = 0; mi < 4; mi++)
#pragma unroll
                for (int np = 0; np < 2; np++)
#pragma unroll
                    for (int ns = 0; ns < 2; ns++) {
                        float* c = acc[mi][np * 2 + ns];
                        mma16816(c, ah[mi], &bh[np][ns * 2]);
                        mma16816(c, ah[mi], &bl[np][ns * 2]);
                        mma16816(c, al[mi], &bh[np][ns * 2]);
                    }
        }
        __syncthreads();
    }

    const int mrow = lane >> 2;
    const int ncol = (lane & 3) * 2;
#pragma unroll
    for (int mi = 0; mi < 4; mi++) {
#pragma unroll
        for (int ni = 0; ni < 4; ni++) {
            int gn = n0 + wn * 32 + ni * 8 + ncol;
            float b0 = bias[gn], b1 = bias[gn + 1];
#pragma unroll
            for (int half = 0; half < 2; half++) {
                int gm = m0 + wm * 64 + mi * 16 + mrow + half * 8;
                float v0 = acc[mi][ni][half * 2 + 0] + b0;
                float v1 = acc[mi][ni][half * 2 + 1] + b1;
                if (EPI == 0) {
                    int which = gn / EMBED;
                    int rem = gn - which * EMBED;
                    int h = rem / HDIM, d = rem - h * HDIM;
                    int bb2 = gm >> 10, ss = gm & 1023;
                    float scale = (which == 0) ? QSC2 : 1.0f;
                    __half* dstb = (which == 0) ? g_qt : (which == 1) ? g_kt : g_vt;
                    size_t idx = (((size_t)bb2 * NHEAD + h) * HDIM + d) * SEQ + ss;
                    dstb[idx]       = __float2half_rn(v0 * scale);
                    dstb[idx + SEQ] = __float2half_rn(v1 * scale);
                } else {
                    *(float2*)(out + (size_t)gm * EMBED + gn) = make_float2(v0, v1);
                }
            }
        }
    }
}

// ============================================================================
// Flash attention on HMMA fp16.
// CTA: 128 queries, 8 warps (each m16). Keys in 16 blocks of 64.
// All tiles [80 rows][128 B] SW128-swizzled. Scores in log2 domain.
// ============================================================================
__global__ __launch_bounds__(256) void attn_kernel()
{
    extern __shared__ char smem[];
    const uint32_t sb = smem_u32(smem);
    const uint32_t sQ = sb;                       // 2 tiles x 10240
    const uint32_t sKV[2] = { sb + 20480, sb + 40960 };  // each: K(10240) + V(10240)

    const int tid = threadIdx.x;
    const int lane = tid & 31;
    const int wid = tid >> 5;
    const int bh = blockIdx.y;
    const int q0 = blockIdx.x * 128;

    const __half* Qt = g_qt + (size_t)bh * HDIM * SEQ;
    const __half* Kt = g_kt + (size_t)bh * HDIM * SEQ;
    const __half* Vt = g_vt + (size_t)bh * HDIM * SEQ;

    // ---- load Q tiles (two [80][64] tiles)
#pragma unroll
    for (int j = 0; j < 5; j++) {
        int idx = tid + j * 256;          // 0..1279
        int t = idx / 640;
        int r = (idx - t * 640) >> 3;
        int u = idx & 7;
        CP_ASYNC16(sQ + t * 10240 + swz(r * 128 + u * 16),
                   Qt + (size_t)r * SEQ + q0 + t * 64 + u * 8);
    }
    // KV block 0
#pragma unroll
    for (int j = 0; j < 5; j++) {
        int idx = tid + j * 256;
        int which = idx / 640;
        int r = (idx - which * 640) >> 3;
        int u = idx & 7;
        const __half* src = (which ? Vt : Kt) + (size_t)r * SEQ + 0 + u * 8;
        CP_ASYNC16(sKV[0] + which * 10240 + swz(r * 128 + u * 16), src);
    }
    CP_COMMIT();
    CP_WAIT(0);
    __syncthreads();

    // ---- Q fragments (held for whole kernel)
    uint32_t aq[5][4];
    {
        const int g = lane >> 3;
        const uint32_t qtile = sQ + (wid >> 2) * 10240;
        const uint32_t colb = (wid & 3) * 32 + (g & 1) * 16;
#pragma unroll
        for (int ks = 0; ks < 5; ks++) {
            uint32_t row = ks * 16 + (g >> 1) * 8 + (lane & 7);
            ldsm_x4t(qtile + swz(row * 128 + colb), aq[ks][0], aq[ks][1], aq[ks][2], aq[ks][3]);
        }
    }

    float m0 = -1e30f, m1 = -1e30f, l0 = 0.f, l1 = 0.f;
    float o[10][4];
#pragma unroll
    for (int i = 0; i < 10; i++)
#pragma unroll
        for (int e = 0; e < 4; e++) o[i][e] = 0.f;

    const int g = lane >> 3;

    for (int kt = 0; kt < 16; kt++) {
        if (kt + 1 < 16) {
            const int k0n = (kt + 1) * 64;
            const uint32_t dst = sKV[(kt + 1) & 1];
#pragma unroll
            for (int j = 0; j < 5; j++) {
                int idx = tid + j * 256;
                int which = idx / 640;
                int r = (idx - which * 640) >> 3;
                int u = idx & 7;
                const __half* src = (which ? Vt : Kt) + (size_t)r * SEQ + k0n + u * 8;
                CP_ASYNC16(dst + which * 10240 + swz(r * 128 + u * 16), src);
            }
            CP_COMMIT();
            CP_WAIT(1);
        } else {
            CP_WAIT(0);
        }
        __syncthreads();

        const uint32_t baseK = sKV[kt & 1];
        const uint32_t baseV = baseK + 10240;

        // ---- scores S = Q K^T (log2-scaled)
        float c[8][4];
#pragma unroll
        for (int i = 0; i < 8; i++)
#pragma unroll
            for (int e = 0; e < 4; e++) c[i][e] = 0.f;

#pragma unroll
        for (int ks = 0; ks < 5; ks++) {
#pragma unroll
            for (int nt2 = 0; nt2 < 4; nt2++) {
                uint32_t row = ks * 16 + (g & 1) * 8 + (lane & 7);
                uint32_t colb = nt2 * 32 + (g >> 1) * 16;
                uint32_t b[4];
                ldsm_x4t(baseK + swz(row * 128 + colb), b[0], b[1], b[2], b[3]);
                mma16816h(c[2 * nt2],     aq[ks], &b[0]);
                mma16816h(c[2 * nt2 + 1], aq[ks], &b[2]);
            }
        }

        // ---- online softmax (base-2)
        float mx0 = c[0][0], mx1 = c[0][2];
#pragma unroll
        for (int nt = 0; nt < 8; nt++) {
            mx0 = fmaxf(mx0, fmaxf(c[nt][0], c[nt][1]));
            mx1 = fmaxf(mx1, fmaxf(c[nt][2], c[nt][3]));
        }
        mx0 = fmaxf(mx0, __shfl_xor_sync(0xffffffffu, mx0, 1));
        mx0 = fmaxf(mx0, __shfl_xor_sync(0xffffffffu, mx0, 2));
        mx1 = fmaxf(mx1, __shfl_xor_sync(0xffffffffu, mx1, 1));
        mx1 = fmaxf(mx1, __shfl_xor_sync(0xffffffffu, mx1, 2));
        float mn0 = fmaxf(m0, mx0), mn1 = fmaxf(m1, mx1);
        float al0 = ex2(m0 - mn0), al1 = ex2(m1 - mn1);
        float s0 = 0.f, s1 = 0.f;
#pragma unroll
        for (int nt = 0; nt < 8; nt++) {
            c[nt][0] = ex2(c[nt][0] - mn0);
            c[nt][1] = ex2(c[nt][1] - mn0);
            c[nt][2] = ex2(c[nt][2] - mn1);
            c[nt][3] = ex2(c[nt][3] - mn1);
            s0 += c[nt][0] + c[nt][1];
            s1 += c[nt][2] + c[nt][3];
        }
        s0 += __shfl_xor_sync(0xffffffffu, s0, 1);
        s0 += __shfl_xor_sync(0xffffffffu, s0, 2);
        s1 += __shfl_xor_sync(0xffffffffu, s1, 1);
        s1 += __shfl_xor_sync(0xffffffffu, s1, 2);
        l0 = l0 * al0 + s0; l1 = l1 * al1 + s1;
        m0 = mn0; m1 = mn1;
#pragma unroll
        for (int i = 0; i < 10; i++) {
            o[i][0] *= al0; o[i][1] *= al0;
            o[i][2] *= al1; o[i][3] *= al1;
        }

        // ---- pack P to fp16 A-fragments
        uint32_t ap[4][4];
#pragma unroll
        for (int t = 0; t < 4; t++) {
            ap[t][0] = packh2(c[2 * t][0],     c[2 * t][1]);
            ap[t][1] = packh2(c[2 * t][2],     c[2 * t][3]);
            ap[t][2] = packh2(c[2 * t + 1][0], c[2 * t + 1][1]);
            ap[t][3] = packh2(c[2 * t + 1][2], c[2 * t + 1][3]);
        }

        // ---- O += P V  (V^T tile [d][key], non-trans ldmatrix)
        const int b_n = ((lane >> 4) & 1) * 8 + (lane & 7);
        const int b_k = ((lane >> 3) & 1) * 16;
#pragma unroll
        for (int t = 0; t < 4; t++) {
#pragma unroll
            for (int dp = 0; dp < 5; dp++) {
                uint32_t row = dp * 16 + b_n;
                uint32_t colb = t * 32 + b_k;
                uint32_t v[4];
                ldsm_x4(baseV + swz(row * 128 + colb), v[0], v[1], v[2], v[3]);
                mma16816h(o[2 * dp],     ap[t], &v[0]);
                mma16816h(o[2 * dp + 1], ap[t], &v[2]);
            }
        }
        __syncthreads();
    }

    // ---- epilogue: ctx = O/l -> bf16 hi/lo [B,S,E]
    const float il0 = 1.0f / l0, il1 = 1.0f / l1;
    const int b = bh >> 4;
    const int h = bh & 15;
    const int gid = lane >> 2, tig = lane & 3;
    const int qr0 = q0 + wid * 16 + gid;
    const int qr1 = qr0 + 8;
#pragma unroll
    for (int dt = 0; dt < 10; dt++) {
        int e = h * HDIM + dt * 8 + tig * 2;
        size_t i0 = ((size_t)(b * SEQ + qr0)) * EMBED + e;
        size_t i1 = ((size_t)(b * SEQ + qr1)) * EMBED + e;
        float v00 = o[dt][0] * il0, v01 = o[dt][1] * il0;
        float v10 = o[dt][2] * il1, v11 = o[dt][3] * il1;
        __nv_bfloat16 h00 = __float2bfloat16_rn(v00), h01 = __float2bfloat16_rn(v01);
        __nv_bfloat16 h10 = __float2bfloat16_rn(v10), h11 = __float2bfloat16_rn(v11);
        *(__nv_bfloat162*)&g_ch[i0] = __nv_bfloat162(h00, h01);
        *(__nv_bfloat162*)&g_ch[i1] = __nv_bfloat162(h10, h11);
        __nv_bfloat16 l00 = __float2bfloat16_rn(v00 - __bfloat162float(h00));
        __nv_bfloat16 l01 = __float2bfloat16_rn(v01 - __bfloat162float(h01));
        __nv_bfloat16 l10 = __float2bfloat16_rn(v10 - __bfloat162float(h10));
        __nv_bfloat16 l11 = __float2bfloat16_rn(v11 - __bfloat162float(h11));
        *(__nv_bfloat162*)&g_cl[i0] = __nv_bfloat162(l00, l01);
        *(__nv_bfloat162*)&g_cl[i1] = __nv_bfloat162(l10, l11);
    }
}

// ============================================================================
extern "C" void kernel_launch(void* const* d_in, const int* in_sizes, int n_in,
                              void* d_out, int out_size)
{
    const float* x      = (const float*)d_in[0];
    const float* w_qkv  = (const float*)d_in[1];
    const float* b_qkv  = (const float*)d_in[2];
    const float* w_proj = (const float*)d_in[3];
    const float* b_proj = (const float*)d_in[4];
    float* out = (float*)d_out;

    __nv_bfloat16 *xh, *xl, *wqh, *wql, *wph, *wpl, *ch, *cl;
    cudaGetSymbolAddress((void**)&xh,  g_xh);
    cudaGetSymbolAddress((void**)&xl,  g_xl);
    cudaGetSymbolAddress((void**)&wqh, g_wqh);
    cudaGetSymbolAddress((void**)&wql, g_wql);
    cudaGetSymbolAddress((void**)&wph, g_wph);
    cudaGetSymbolAddress((void**)&wpl, g_wpl);
    cudaGetSymbolAddress((void**)&ch,  g_ch);
    cudaGetSymbolAddress((void**)&cl,  g_cl);

    const int mm_smem = 2 * 4 * BM * 128;   // 131072 B
    cudaFuncSetAttribute(mm3_kernel<0>, cudaFuncAttributeMaxDynamicSharedMemorySize, mm_smem);
    cudaFuncSetAttribute(mm3_kernel<1>, cudaFuncAttributeMaxDynamicSharedMemorySize, mm_smem);
    const int attn_smem = 20480 + 2 * 20480;  // 61440 B
    cudaFuncSetAttribute(attn_kernel, cudaFuncAttributeMaxDynamicSharedMemorySize, attn_smem);

    // prep
    xsplit_kernel<<<(NTOK * EMBED / 4 + 255) / 256, 256>>>(x, xh, xl, NTOK * EMBED / 4);
    {
        dim3 g(QKV_N / 32, EMBED / 32);
        wsplit_kernel<<<g, 256>>>(w_qkv, wqh, wql, EMBED, QKV_N);
    }
    {
        dim3 g(EMBED / 32, EMBED / 32);
        wsplit_kernel<<<g, 256>>>(w_proj, wph, wpl, EMBED, EMBED);
    }

    // QKV GEMM (writes Q^T/K^T/V^T fp16)
    {
        dim3 g(QKV_N / BN, NTOK / BM);
        mm3_kernel<0><<<g, 256, mm_smem>>>(xh, xl, wqh, wql, b_qkv, nullptr);
    }
    // attention
    {
        dim3 g(SEQ / 128, BATCH * NHEAD);
        attn_kernel<<<g, 256, attn_smem>>>();
    }
    // output projection
    {
        dim3 g(EMBED / BN, NTOK / BM);
        mm3_kernel<1><<<g, 256, mm_smem>>>(ch, cl, wph, wpl, b_proj, out);
    }
}